// round 1
// baseline (speedup 1.0000x reference)
#include <cuda_runtime.h>
#include <math.h>
#include <stdint.h>

// Problem dims
#define Bb 64
#define Tt 1024
#define Dd 512
#define Hh 512

// Recurrence partition: 16 row-groups (4 batch rows each) x 8 col-blocks (64 cols each)
#define NGROUP 16
#define NCOLB  8
#define RROWS  4
#define CCOLS  64
#define WPITCH 516   // 512 + 4 pad floats -> conflict-free LDS.128 across columns

// Per-(step, group) arrival counters for the 8-CTA mini-barrier.
__device__ int g_cnt[Tt * NGROUP];

__global__ void clear_cnt_kernel() {
    int i = blockIdx.x * blockDim.x + threadIdx.x;
    if (i < Tt * NGROUP) g_cnt[i] = 0;
}

// ---------------------------------------------------------------------------
// Phase 1: xw = x @ Wx + b   (M=B*T=65536, N=H=512, K=D=512), staged into out.
// Classic smem-tiled fp32 GEMM: BM=64, BN=64, BK=16, 256 threads, 4x4 microtile.
// ---------------------------------------------------------------------------
__global__ __launch_bounds__(256) void xw_gemm_kernel(
    const float* __restrict__ x,
    const float* __restrict__ W,     // (D+H, H); rows [0,D) = Wx
    const float* __restrict__ bias,  // (H,)
    float* __restrict__ out)         // (B*T, H)
{
    __shared__ float As[16][64];   // [k][m]
    __shared__ float Bs[16][64];   // [k][n]
    const int tid = threadIdx.x;
    const int tx = tid & 15, ty = tid >> 4;
    const int m0 = blockIdx.y * 64;
    const int n0 = blockIdx.x * 64;

    float acc[4][4] = {};

    for (int k0 = 0; k0 < Dd; k0 += 16) {
        // Load A tile 64x16 (transposed into [k][m])
        {
            int r  = tid >> 2;           // 0..63
            int c4 = (tid & 3) * 4;      // 0,4,8,12
            float4 v = *reinterpret_cast<const float4*>(
                &x[(size_t)(m0 + r) * Dd + k0 + c4]);
            As[c4 + 0][r] = v.x; As[c4 + 1][r] = v.y;
            As[c4 + 2][r] = v.z; As[c4 + 3][r] = v.w;
        }
        // Load B tile 16x64
        {
            int r  = tid >> 4;           // 0..15
            int c4 = (tid & 15) * 4;     // 0..60
            float4 v = *reinterpret_cast<const float4*>(
                &W[(size_t)(k0 + r) * Hh + n0 + c4]);
            *reinterpret_cast<float4*>(&Bs[r][c4]) = v;
        }
        __syncthreads();

        #pragma unroll
        for (int kk = 0; kk < 16; kk++) {
            float4 a = *reinterpret_cast<const float4*>(&As[kk][ty * 4]);
            float4 b = *reinterpret_cast<const float4*>(&Bs[kk][tx * 4]);
            float av[4] = {a.x, a.y, a.z, a.w};
            float bv[4] = {b.x, b.y, b.z, b.w};
            #pragma unroll
            for (int i = 0; i < 4; i++)
                #pragma unroll
                for (int j = 0; j < 4; j++)
                    acc[i][j] = fmaf(av[i], bv[j], acc[i][j]);
        }
        __syncthreads();
    }

    #pragma unroll
    for (int i = 0; i < 4; i++) {
        int m = m0 + ty * 4 + i;
        #pragma unroll
        for (int j = 0; j < 4; j++) {
            int n = n0 + tx * 4 + j;
            out[(size_t)m * Hh + n] = acc[i][j] + bias[n];
        }
    }
}

// ---------------------------------------------------------------------------
// Phase 2: persistent recurrence. 128 CTAs (16 groups x 8 col-blocks), each
// holds its 512x64 Wh slice in SMEM for all 1024 steps. h state lives in the
// output tensor: out[:, t, :] starts as xw_t and is overwritten by h_t.
// Sync per step: 8-CTA barrier per row-group via L2 atomic counters.
// ---------------------------------------------------------------------------
extern __shared__ float smem[];

__device__ __forceinline__ void group_barrier(int t, int g) {
    __threadfence();            // make this CTA's STGs visible at L2
    __syncthreads();
    if (threadIdx.x == 0) {
        int* p = &g_cnt[t * NGROUP + g];
        atomicAdd(p, 1);
        while (*(volatile int*)p < NCOLB) { }
    }
    __syncthreads();
}

__global__ __launch_bounds__(256) void recur_kernel(
    const float* __restrict__ W,   // rows [D, D+H) = Wh
    float* __restrict__ out)       // (B, T, H) flattened; holds xw, becomes h
{
    float* ws = smem;                       // [CCOLS][WPITCH] transposed Wh slice
    float* hs = smem + CCOLS * WPITCH;      // [RROWS][Hh] current h rows

    const int tid  = threadIdx.x;
    const int j    = blockIdx.x;            // col block 0..7
    const int g    = blockIdx.y;            // row group 0..15
    const int col0 = j * CCOLS;
    const int c    = tid & 63;              // local column
    const int r    = tid >> 6;              // local row 0..3
    const int row  = g * RROWS + r;         // batch index

    // Load Wh slice into smem, transposed: ws[c][k]
    for (int i = tid; i < CCOLS * Hh; i += 256) {
        int k  = i >> 6;
        int cc = i & 63;
        ws[cc * WPITCH + k] = W[(size_t)(Dd + k) * Hh + col0 + cc];
    }
    __syncthreads();

    // t = 0: h_0 input state is zero -> h = tanh(xw_0)
    {
        size_t o = ((size_t)row * Tt) * Hh + col0 + c;
        out[o] = tanhf(__ldcg(&out[o]));
    }

    const float4* wp = reinterpret_cast<const float4*>(ws + c * WPITCH);
    const float4* hp = reinterpret_cast<const float4*>(hs + r * Hh);

    for (int t = 1; t < Tt; t++) {
        group_barrier(t - 1, g);   // all 8 CTAs of this group finished step t-1

        // Load h_{t-1} rows (4 x 512 fp32) from out via L2 (bypass L1)
        for (int i = tid; i < (RROWS * Hh) / 4; i += 256) {   // 512 float4s
            int rr = i >> 7;
            int kk = i & 127;
            float4 v = __ldcg(reinterpret_cast<const float4*>(
                &out[((size_t)(g * RROWS + rr) * Tt + (t - 1)) * Hh + kk * 4]));
            reinterpret_cast<float4*>(hs)[i] = v;
        }
        __syncthreads();

        // acc = dot(h_{t-1}[row, :], Wh[:, col]) with 4 accumulators
        float a0 = 0.f, a1 = 0.f, a2 = 0.f, a3 = 0.f;
        #pragma unroll 8
        for (int kk = 0; kk < Hh / 4; kk++) {
            float4 w = wp[kk];
            float4 h = hp[kk];
            a0 = fmaf(w.x, h.x, a0);
            a1 = fmaf(w.y, h.y, a1);
            a2 = fmaf(w.z, h.z, a2);
            a3 = fmaf(w.w, h.w, a3);
        }

        size_t o = ((size_t)row * Tt + t) * Hh + col0 + c;
        float v = tanhf((a0 + a1) + (a2 + a3) + __ldcg(&out[o]));
        out[o] = v;
    }
}

// ---------------------------------------------------------------------------
extern "C" void kernel_launch(void* const* d_in, const int* in_sizes, int n_in,
                              void* d_out, int out_size)
{
    const float* x    = (const float*)d_in[0];
    const float* W    = (const float*)d_in[1];
    const float* bias = (const float*)d_in[2];
    float* out        = (float*)d_out;

    // Phase 1: stage xw into out
    dim3 gg(Hh / 64, (Bb * Tt) / 64);
    xw_gemm_kernel<<<gg, 256>>>(x, W, bias, out);

    // Reset per-step barrier counters (needed every graph replay)
    clear_cnt_kernel<<<(Tt * NGROUP + 255) / 256, 256>>>();

    // Phase 2: persistent recurrence (128 CTAs <= 148 SMs, all co-resident
    // since 140 KB smem limits occupancy to 1 CTA/SM)
    const size_t SMEM = (size_t)(CCOLS * WPITCH + RROWS * Hh) * sizeof(float);
    cudaFuncSetAttribute(recur_kernel,
                         cudaFuncAttributeMaxDynamicSharedMemorySize, (int)SMEM);
    recur_kernel<<<dim3(NCOLB, NGROUP), 256, SMEM>>>(W, out);
}

// round 2
// speedup vs baseline: 1.8251x; 1.8251x over previous
#include <cuda_runtime.h>
#include <math.h>
#include <stdint.h>

// Problem dims
#define Bb 64
#define Tt 1024
#define Dd 512
#define Hh 512

// Recurrence partition: 16 row-groups (4 batch rows) x 8 col-blocks (64 cols)
#define NGROUP 16
#define NCOLB  8
#define RROWS  4
#define CCOLS  64

// Per-(step, group, cta) publish flags
__device__ int g_flag[Tt * NGROUP * NCOLB];

__global__ void clear_flags_kernel() {
    int i = blockIdx.x * blockDim.x + threadIdx.x;
    if (i < Tt * NGROUP * NCOLB) g_flag[i] = 0;
}

// ---- packed f32x2 helpers (FFMA2: PTX-only, ptxas won't auto-fuse) ----
__device__ __forceinline__ unsigned long long fma2(unsigned long long a,
                                                   unsigned long long b,
                                                   unsigned long long c) {
    unsigned long long d;
    asm("fma.rn.f32x2 %0, %1, %2, %3;" : "=l"(d) : "l"(a), "l"(b), "l"(c));
    return d;
}
__device__ __forceinline__ unsigned long long pack2(float lo, float hi) {
    unsigned long long d;
    asm("mov.b64 %0, {%1, %2};" : "=l"(d) : "f"(lo), "f"(hi));
    return d;
}
__device__ __forceinline__ float2 unpack2(unsigned long long v) {
    float2 r;
    asm("mov.b64 {%0, %1}, %2;" : "=f"(r.x), "=f"(r.y) : "l"(v));
    return r;
}

// ---------------------------------------------------------------------------
// Phase 1: xw = x @ Wx + b  (M=65536, N=512, K=512) staged into out.
// BM=128, BN=64, BK=16, 256 threads, 8x4 microtile, FFMA2 inner product.
// A m-pairs are read directly from smem as packed 64-bit operands (no movs);
// only B needs broadcast-packing (4 movs / kk).
// ---------------------------------------------------------------------------
#define BM 128
#define BN 64
#define BK 16

__global__ __launch_bounds__(256) void xw_gemm_kernel(
    const float* __restrict__ x,
    const float* __restrict__ W,     // (D+H, H); rows [0,D) = Wx
    const float* __restrict__ bias,
    float* __restrict__ out)         // (B*T, H)
{
    __shared__ float As[BK][BM];   // [k][m]
    __shared__ float Bs[BK][BN];   // [k][n]
    const int tid = threadIdx.x;
    const int tx = tid & 15;       // n: 4 cols
    const int ty = tid >> 4;       // m: 8 rows
    const int m0 = blockIdx.y * BM;
    const int n0 = blockIdx.x * BN;

    unsigned long long acc2[4][4];   // [m-pair][n]
    #pragma unroll
    for (int i = 0; i < 4; i++)
        #pragma unroll
        for (int jj = 0; jj < 4; jj++) acc2[i][jj] = 0ull;

    for (int k0 = 0; k0 < Dd; k0 += BK) {
        // A tile 128x16 -> As[k][m] (coalesced LDG.128 along k, strided STS)
        #pragma unroll
        for (int it = 0; it < 2; it++) {
            int idx = tid + it * 256;          // 0..511
            int m   = idx >> 2;                // 0..127
            int kq  = (idx & 3) * 4;
            float4 v = *reinterpret_cast<const float4*>(
                &x[(size_t)(m0 + m) * Dd + k0 + kq]);
            As[kq + 0][m] = v.x; As[kq + 1][m] = v.y;
            As[kq + 2][m] = v.z; As[kq + 3][m] = v.w;
        }
        // B tile 16x64
        {
            int rr = tid >> 4;
            int c4 = (tid & 15) * 4;
            float4 v = *reinterpret_cast<const float4*>(
                &W[(size_t)(k0 + rr) * Hh + n0 + c4]);
            *reinterpret_cast<float4*>(&Bs[rr][c4]) = v;
        }
        __syncthreads();

        #pragma unroll
        for (int kk = 0; kk < BK; kk++) {
            const ulonglong2* ap =
                reinterpret_cast<const ulonglong2*>(&As[kk][ty * 8]);
            ulonglong2 a01 = ap[0], a23 = ap[1];
            unsigned long long av[4] = {a01.x, a01.y, a23.x, a23.y};
            float4 b = *reinterpret_cast<const float4*>(&Bs[kk][tx * 4]);
            unsigned long long bv[4] = {pack2(b.x, b.x), pack2(b.y, b.y),
                                        pack2(b.z, b.z), pack2(b.w, b.w)};
            #pragma unroll
            for (int i = 0; i < 4; i++)
                #pragma unroll
                for (int jj = 0; jj < 4; jj++)
                    acc2[i][jj] = fma2(av[i], bv[jj], acc2[i][jj]);
        }
        __syncthreads();
    }

    float4 bb = *reinterpret_cast<const float4*>(&bias[n0 + tx * 4]);
    #pragma unroll
    for (int i = 0; i < 4; i++) {
        float2 u[4];
        #pragma unroll
        for (int jj = 0; jj < 4; jj++) u[jj] = unpack2(acc2[i][jj]);
        int m = m0 + ty * 8 + 2 * i;
        float4 lo = make_float4(u[0].x + bb.x, u[1].x + bb.y,
                                u[2].x + bb.z, u[3].x + bb.w);
        float4 hi = make_float4(u[0].y + bb.x, u[1].y + bb.y,
                                u[2].y + bb.z, u[3].y + bb.w);
        *reinterpret_cast<float4*>(&out[(size_t)m * Hh + n0 + tx * 4]) = lo;
        *reinterpret_cast<float4*>(&out[(size_t)(m + 1) * Hh + n0 + tx * 4]) = hi;
    }
}

// ---------------------------------------------------------------------------
// Phase 2: persistent recurrence, Wh slice in REGISTERS.
// 128 CTAs (16 groups x 8 col-blocks), 256 threads = (64 cols x 4 k-chunks).
// Each thread holds 128 Wh values (64 packed f32x2 regs) for its column/chunk.
// Per step: poll peer flags -> stage h (8KB) to smem -> broadcast-LDS + FFMA2
// -> smem reduce over 4 k-chunks -> tanh -> STG -> release flag.
// ---------------------------------------------------------------------------
__global__ __launch_bounds__(256, 1) void recur_kernel(
    const float* __restrict__ W,   // rows [D, D+H) = Wh
    float* __restrict__ out)       // (B, T, H); holds xw, becomes h
{
    __shared__ float hs[RROWS][Hh];          // 8 KB: h_{t-1} rows
    __shared__ float red[4][RROWS][CCOLS];   // 4 KB: k-chunk partials

    const int tid  = threadIdx.x;
    const int j    = blockIdx.x;             // col block 0..7
    const int g    = blockIdx.y;             // row group 0..15
    const int col0 = j * CCOLS;
    const int c    = tid & 63;               // column within block
    const int q    = tid >> 6;               // k-chunk 0..3 (uniform per warp)
    const int r2   = tid >> 6;               // epilogue row
    const int ce   = tid & 63;               // epilogue col

    // Load Wh slice into registers: w2[i] = (Wh[q*128+2i][col], Wh[q*128+2i+1][col])
    unsigned long long w2[64];
    #pragma unroll
    for (int i = 0; i < 64; i++) {
        int k = q * 128 + 2 * i;
        float a = W[(size_t)(Dd + k) * Hh + col0 + c];
        float b = W[(size_t)(Dd + k + 1) * Hh + col0 + c];
        w2[i] = pack2(a, b);
    }

    // t = 0: h_0 = 0 -> h = tanh(xw_0)
    {
        size_t o = ((size_t)(g * RROWS + r2) * Tt) * Hh + col0 + ce;
        out[o] = tanhf(__ldcg(&out[o]));
        __syncthreads();
        if (tid == 0)
            asm volatile("st.global.release.gpu.b32 [%0], %1;"
                         :: "l"(&g_flag[(0 * NGROUP + g) * NCOLB + j]), "r"(1)
                         : "memory");
    }

    for (int t = 1; t < Tt; t++) {
        // Wait for all 8 CTAs of this group to publish h_{t-1}
        if (tid < NCOLB) {
            const int* f = &g_flag[((t - 1) * NGROUP + g) * NCOLB + tid];
            int v;
            do {
                asm volatile("ld.global.acquire.gpu.b32 %0, [%1];"
                             : "=r"(v) : "l"(f) : "memory");
            } while (v == 0);
        }
        __syncthreads();

        // Prefetch this thread's xw element (overlaps h staging)
        float xw_v = __ldcg(&out[((size_t)(g * RROWS + r2) * Tt + t) * Hh + col0 + ce]);

        // Stage h_{t-1}: 4 rows x 512 fp32 from L2
        #pragma unroll
        for (int it = 0; it < 2; it++) {
            int idx = tid + it * 256;   // 0..511 float4s
            int rr  = idx >> 7;
            int kk  = idx & 127;
            float4 v = __ldcg(reinterpret_cast<const float4*>(
                &out[((size_t)(g * RROWS + rr) * Tt + (t - 1)) * Hh + kk * 4]));
            *reinterpret_cast<float4*>(&hs[rr][kk * 4]) = v;
        }
        __syncthreads();

        // Partial dots: rows 0..3, column c, k-chunk q. h reads are warp-broadcast.
        unsigned long long acc[RROWS] = {0ull, 0ull, 0ull, 0ull};
        const ulonglong2* hp0 = reinterpret_cast<const ulonglong2*>(&hs[0][q * 128]);
        const ulonglong2* hp1 = reinterpret_cast<const ulonglong2*>(&hs[1][q * 128]);
        const ulonglong2* hp2 = reinterpret_cast<const ulonglong2*>(&hs[2][q * 128]);
        const ulonglong2* hp3 = reinterpret_cast<const ulonglong2*>(&hs[3][q * 128]);
        #pragma unroll
        for (int i = 0; i < 32; i++) {
            ulonglong2 h0 = hp0[i], h1 = hp1[i], h2 = hp2[i], h3 = hp3[i];
            acc[0] = fma2(w2[2 * i], h0.x, acc[0]);
            acc[1] = fma2(w2[2 * i], h1.x, acc[1]);
            acc[2] = fma2(w2[2 * i], h2.x, acc[2]);
            acc[3] = fma2(w2[2 * i], h3.x, acc[3]);
            acc[0] = fma2(w2[2 * i + 1], h0.y, acc[0]);
            acc[1] = fma2(w2[2 * i + 1], h1.y, acc[1]);
            acc[2] = fma2(w2[2 * i + 1], h2.y, acc[2]);
            acc[3] = fma2(w2[2 * i + 1], h3.y, acc[3]);
        }
        #pragma unroll
        for (int rr = 0; rr < RROWS; rr++) {
            float2 u = unpack2(acc[rr]);
            red[q][rr][c] = u.x + u.y;
        }
        __syncthreads();

        // Reduce 4 k-chunks, add xw, tanh, publish
        float s = red[0][r2][ce] + red[1][r2][ce] + red[2][r2][ce] + red[3][r2][ce];
        float v = tanhf(s + xw_v);
        out[((size_t)(g * RROWS + r2) * Tt + t) * Hh + col0 + ce] = v;
        __syncthreads();
        if (tid == 0)
            asm volatile("st.global.release.gpu.b32 [%0], %1;"
                         :: "l"(&g_flag[(t * NGROUP + g) * NCOLB + j]), "r"(1)
                         : "memory");
    }
}

// ---------------------------------------------------------------------------
extern "C" void kernel_launch(void* const* d_in, const int* in_sizes, int n_in,
                              void* d_out, int out_size)
{
    const float* x    = (const float*)d_in[0];
    const float* W    = (const float*)d_in[1];
    const float* bias = (const float*)d_in[2];
    float* out        = (float*)d_out;

    // Phase 1: stage xw into out
    dim3 gg(Hh / BN, (Bb * Tt) / BM);
    xw_gemm_kernel<<<gg, 256>>>(x, W, bias, out);

    // Reset publish flags (every graph replay)
    clear_flags_kernel<<<(Tt * NGROUP * NCOLB + 255) / 256, 256>>>();

    // Phase 2: persistent recurrence (128 CTAs, all co-resident)
    recur_kernel<<<dim3(NCOLB, NGROUP), 256>>>(W, out);
}